// round 1
// baseline (speedup 1.0000x reference)
#include <cuda_runtime.h>
#include <math.h>

#define B_ 8
#define N_ 2048
#define K_ 4
#define CB 512
#define TM 64
#define TN 64
#define KC 32
#define PP 8

// ---------------- scratch (device globals; no allocation) ----------------
__device__ float g_xcn[(size_t)B_*CB*N_];    // features, [B][C][N] (cat layout)
__device__ float g_xnc[(size_t)B_*N_*CB];    // features, [B][N][C] (cat layout)
__device__ float g_x0nc[(size_t)B_*N_*4];    // input transposed, padded C=4
__device__ int   g_idx[(size_t)B_*N_*K_];
__device__ float g_xx[(size_t)B_*N_];
__device__ float g_mx[(size_t)B_*N_*256];
__device__ float g_mn[(size_t)B_*N_*256];
__device__ float g_y5[(size_t)B_*N_*512];
__device__ float g_sum[512];
__device__ float g_ssq[512];
__device__ float4 g_wT4[65536];              // packed transposed weights

// ---------------- prep kernels ----------------
__global__ void k_prep_x0(const float* __restrict__ x) {
    int t = blockIdx.x*blockDim.x + threadIdx.x;
    if (t >= B_*N_) return;
    int b = t / N_, n = t - b*N_;
    float4 v;
    v.x = x[(b*3+0)*N_ + n];
    v.y = x[(b*3+1)*N_ + n];
    v.z = x[(b*3+2)*N_ + n];
    v.w = 0.f;
    ((float4*)g_x0nc)[t] = v;
}

// pack w[O][parts*realC] -> g_wT4 part-major: [part][padC/4][O] float4
__global__ void k_prep_w(const float* __restrict__ w, int realC, int padC,
                         int O, int parts) {
    int c4n = padC >> 2;
    int total = parts * c4n * O;
    int t = blockIdx.x*blockDim.x + threadIdx.x;
    if (t >= total) return;
    int o = t % O; int r = t / O; int c4 = r % c4n; int part = r / c4n;
    float4 v;
    float* pv = (float*)&v;
    #pragma unroll
    for (int j = 0; j < 4; j++) {
        int c = c4*4 + j;
        pv[j] = (c < realC) ? w[o*(parts*realC) + part*realC + c] : 0.f;
    }
    g_wT4[t] = v;
}

__global__ void k_clear() {
    int t = blockIdx.x*blockDim.x + threadIdx.x;
    if (t < 512) { g_sum[t] = 0.f; g_ssq[t] = 0.f; }
}

__global__ void k_norms(const float* __restrict__ base, int C, long bstride) {
    int t = blockIdx.x*blockDim.x + threadIdx.x;
    if (t >= B_*N_) return;
    int b = t / N_, n = t - b*N_;
    const float* p = base + (long)b*bstride + n;
    float s = 0.f;
    for (int c = 0; c < C; c++) { float v = p[(long)c*N_]; s += v*v; }
    g_xx[t] = s;
}

// ---------------- knn: tiled distance GEMM + per-row top-4 ----------------
__global__ void __launch_bounds__(256) k_knn(const float* __restrict__ base,
                                             int C, long bstride) {
    extern __shared__ float sm[];
    const int Cp = (C + KC - 1) / KC * KC;
    float* Ash = sm;                       // [Cp][TM]
    float* Bsh = Ash + Cp*TM;              // [KC][TN]
    float* PD  = Bsh + KC*TN;              // [TM][TN+1]
    float* xxc = PD + TM*(TN+1);           // [TN]
    const int b  = blockIdx.y;
    const int n0 = blockIdx.x * TM;
    const float* X = base + (long)b * bstride;
    const int tid = threadIdx.x;
    const int ty = tid >> 4, tx = tid & 15;

    for (int t = tid; t < Cp*TM; t += 256) {
        int c = t / TM, r = t - c*TM;
        Ash[t] = (c < C) ? X[(long)c*N_ + n0 + r] : 0.f;
    }
    float xxr[4];
    #pragma unroll
    for (int i = 0; i < 4; i++) xxr[i] = g_xx[b*N_ + n0 + ty*4 + i];
    __syncthreads();

    float v0 = -3.4e38f, v1 = -3.4e38f, v2 = -3.4e38f, v3 = -3.4e38f;
    int   i0 = 0, i1 = 0, i2 = 0, i3 = 0;

    for (int mb = 0; mb < N_/TN; mb++) {
        const int m0 = mb*TN;
        if (tid < TN) xxc[tid] = g_xx[b*N_ + m0 + tid];
        float acc[4][4];
        #pragma unroll
        for (int i = 0; i < 4; i++)
            #pragma unroll
            for (int j = 0; j < 4; j++) acc[i][j] = 0.f;

        for (int kc = 0; kc < Cp; kc += KC) {
            for (int t = tid; t < KC*TN; t += 256) {
                int c = t / TN, m = t - c*TN;
                int cg = kc + c;
                Bsh[t] = (cg < C) ? X[(long)cg*N_ + m0 + m] : 0.f;
            }
            __syncthreads();
            #pragma unroll
            for (int cc = 0; cc < KC; cc++) {
                float4 a4 = *(const float4*)&Ash[(kc+cc)*TM + ty*4];
                float4 b4 = *(const float4*)&Bsh[cc*TN + tx*4];
                acc[0][0] += a4.x*b4.x; acc[0][1] += a4.x*b4.y;
                acc[0][2] += a4.x*b4.z; acc[0][3] += a4.x*b4.w;
                acc[1][0] += a4.y*b4.x; acc[1][1] += a4.y*b4.y;
                acc[1][2] += a4.y*b4.z; acc[1][3] += a4.y*b4.w;
                acc[2][0] += a4.z*b4.x; acc[2][1] += a4.z*b4.y;
                acc[2][2] += a4.z*b4.z; acc[2][3] += a4.z*b4.w;
                acc[3][0] += a4.w*b4.x; acc[3][1] += a4.w*b4.y;
                acc[3][2] += a4.w*b4.z; acc[3][3] += a4.w*b4.w;
            }
            __syncthreads();
        }
        float xc[4];
        #pragma unroll
        for (int j = 0; j < 4; j++) xc[j] = xxc[tx*4 + j];
        #pragma unroll
        for (int i = 0; i < 4; i++)
            #pragma unroll
            for (int j = 0; j < 4; j++)
                PD[(ty*4+i)*(TN+1) + tx*4 + j] = 2.f*acc[i][j] - xxr[i] - xc[j];
        __syncthreads();

        if (tid < TM) {
            const float* row = &PD[tid*(TN+1)];
            for (int j = 0; j < TN; j++) {
                float p = row[j];
                if (p > v3) {
                    int m = m0 + j;
                    if (p > v1) {
                        if (p > v0) { v3=v2;i3=i2; v2=v1;i2=i1; v1=v0;i1=i0; v0=p;i0=m; }
                        else        { v3=v2;i3=i2; v2=v1;i2=i1; v1=p;i1=m; }
                    } else {
                        if (p > v2) { v3=v2;i3=i2; v2=p;i2=m; }
                        else        { v3=p;i3=m; }
                    }
                }
            }
        }
        __syncthreads();
    }
    if (tid < TM) {
        int bi = (b*N_ + n0 + tid)*K_;
        g_idx[bi+0] = i0; g_idx[bi+1] = i1; g_idx[bi+2] = i2; g_idx[bi+3] = i3;
    }
}

// ---------------- edge conv + minmax over k + channel stats ----------------
__global__ void k_conv_edge(const float* __restrict__ xnc, int CS, int coff,
                            int Cpad, int O,
                            const float4* __restrict__ wn4,
                            const float4* __restrict__ wc4) {
    __shared__ float sf[PP*5*128];
    __shared__ int   sidx[PP*K_];
    const int bid = blockIdx.x;
    const int b  = bid / (N_/PP);
    const int n0 = (bid - b*(N_/PP)) * PP;
    const int o  = threadIdx.x;

    for (int t = o; t < PP*K_; t += O)
        sidx[t] = g_idx[(b*N_ + n0 + (t>>2))*K_ + (t & 3)];
    __syncthreads();
    const int tot = PP*5*Cpad;
    for (int t = o; t < tot; t += O) {
        int c = t % Cpad; int r = t / Cpad; int v = r % 5; int p = r / 5;
        int m = (v == 0) ? (n0 + p) : sidx[p*K_ + v - 1];
        sf[t] = xnc[((long)b*N_ + m)*CS + coff + c];
    }
    __syncthreads();

    float yc[PP]; float yn[PP][K_];
    #pragma unroll
    for (int p = 0; p < PP; p++) {
        yc[p] = 0.f;
        #pragma unroll
        for (int k = 0; k < K_; k++) yn[p][k] = 0.f;
    }
    const int c4n = Cpad >> 2;
    for (int c4 = 0; c4 < c4n; c4++) {
        float4 wn = wn4[c4*O + o];
        float4 wc = wc4[c4*O + o];
        #pragma unroll
        for (int p = 0; p < PP; p++) {
            const float* fb = &sf[p*5*Cpad + c4*4];
            float4 f = *(const float4*)fb;
            yc[p] += wc.x*f.x + wc.y*f.y + wc.z*f.z + wc.w*f.w;
            #pragma unroll
            for (int k = 0; k < K_; k++) {
                float4 g = *(const float4*)(fb + (k+1)*Cpad);
                yn[p][k] += wn.x*g.x + wn.y*g.y + wn.z*g.z + wn.w*g.w;
            }
        }
    }
    float s1 = 0.f, s2 = 0.f;
    #pragma unroll
    for (int p = 0; p < PP; p++) {
        float mmax = -3.4e38f, mmin = 3.4e38f;
        #pragma unroll
        for (int k = 0; k < K_; k++) {
            float y = yn[p][k] + yc[p];
            mmax = fmaxf(mmax, y); mmin = fminf(mmin, y);
            s1 += y; s2 += y*y;
        }
        long oi = ((long)b*N_ + n0 + p)*O + o;
        g_mx[oi] = mmax; g_mn[oi] = mmin;
    }
    atomicAdd(&g_sum[o], s1);
    atomicAdd(&g_ssq[o], s2);
}

__global__ void k_fin_edge(int O, int coff, const float* __restrict__ gm,
                           const float* __restrict__ bt, float invcnt) {
    int t = blockIdx.x*blockDim.x + threadIdx.x;
    if (t >= B_*N_*O) return;
    int o = t % O; int bn = t / O;
    float mean = g_sum[o] * invcnt;
    float var  = g_ssq[o] * invcnt - mean*mean;
    float a  = gm[o] * rsqrtf(var + 1e-5f);
    float c0 = bt[o] - mean*a;
    float z = (a >= 0.f) ? (a*g_mx[t] + c0) : (a*g_mn[t] + c0);
    z = fmaxf(z, 0.f);
    int b = bn / N_, n = bn - b*N_;
    g_xnc[(long)bn*CB + coff + o] = z;
    g_xcn[((long)b*CB + coff + o)*N_ + n] = z;
}

// ---------------- block 5: 512x512 conv + stats ----------------
__global__ void __launch_bounds__(512) k_conv5(const float4* __restrict__ wT) {
    __shared__ float sf[PP*CB];
    const int bid = blockIdx.x;
    const int b  = bid / (N_/PP);
    const int n0 = (bid - b*(N_/PP)) * PP;
    const int o  = threadIdx.x;
    const float* src = &g_xnc[((long)b*N_ + n0)*CB];
    for (int t = o; t < PP*CB; t += 512) sf[t] = src[t];
    __syncthreads();
    float y[PP];
    #pragma unroll
    for (int p = 0; p < PP; p++) y[p] = 0.f;
    for (int c4 = 0; c4 < CB/4; c4++) {
        float4 w = wT[c4*512 + o];
        #pragma unroll
        for (int p = 0; p < PP; p++) {
            float4 f = *(const float4*)&sf[p*CB + c4*4];
            y[p] += w.x*f.x + w.y*f.y + w.z*f.z + w.w*f.w;
        }
    }
    float s1 = 0.f, s2 = 0.f;
    #pragma unroll
    for (int p = 0; p < PP; p++) {
        s1 += y[p]; s2 += y[p]*y[p];
        g_y5[((long)b*N_ + n0 + p)*CB + o] = y[p];
    }
    atomicAdd(&g_sum[o], s1);
    atomicAdd(&g_ssq[o], s2);
}

__global__ void k_fin5(const float* __restrict__ gm, const float* __restrict__ bt,
                       float* __restrict__ out) {
    __shared__ float tile[32][33];
    const int b  = blockIdx.z;
    const int o0 = blockIdx.y*32;
    const int n0 = blockIdx.x*32;
    const int tx = threadIdx.x, ty0 = threadIdx.y;
    const float invcnt = 1.f / (float)(B_*N_);
    int o = o0 + tx;
    float mean = g_sum[o] * invcnt;
    float var  = g_ssq[o] * invcnt - mean*mean;
    float a  = gm[o] * rsqrtf(var + 1e-5f);
    float c0 = bt[o] - mean*a;
    #pragma unroll
    for (int i = 0; i < 4; i++) {
        int ty = ty0 + i*8;
        float y = g_y5[((long)b*N_ + n0 + ty)*CB + o];
        tile[ty][tx] = tanhf(a*y + c0);
    }
    __syncthreads();
    #pragma unroll
    for (int i = 0; i < 4; i++) {
        int ty = ty0 + i*8;
        out[((long)b*CB + o0 + ty)*N_ + n0 + tx] = tile[tx][ty];
    }
}

// ---------------- launch ----------------
extern "C" void kernel_launch(void* const* d_in, const int* in_sizes, int n_in,
                              void* d_out, int out_size) {
    const float* x = (const float*)d_in[0];
    const float* W[5]; const float* G[5]; const float* Bt[5];
    for (int i = 0; i < 5; i++) {
        W[i]  = (const float*)d_in[1 + 3*i];
        G[i]  = (const float*)d_in[2 + 3*i];
        Bt[i] = (const float*)d_in[3 + 3*i];
    }
    float* out = (float*)d_out;

    float* xcn;  cudaGetSymbolAddress((void**)&xcn,  g_xcn);
    float* xnc;  cudaGetSymbolAddress((void**)&xnc,  g_xnc);
    float* x0nc; cudaGetSymbolAddress((void**)&x0nc, g_x0nc);
    float4* wt;  cudaGetSymbolAddress((void**)&wt,   g_wT4);

    cudaFuncSetAttribute(k_knn, cudaFuncAttributeMaxDynamicSharedMemorySize, 57856);

    k_prep_x0<<<(B_*N_ + 255)/256, 256>>>(x);

    struct St { int C, Cpad, O, cin, cout; };
    const St st[4] = { {3,4,64,0,0}, {64,64,64,0,64},
                       {64,64,128,64,128}, {128,128,256,128,256} };

    for (int s = 0; s < 4; s++) {
        const int C = st[s].C, Cpad = st[s].Cpad, O = st[s].O;
        const float* knn_base = (s == 0) ? x : (xcn + (long)st[s].cin * N_);
        const long bstride = (s == 0) ? (long)3*N_ : (long)CB*N_;
        k_norms<<<(B_*N_ + 255)/256, 256>>>(knn_base, C, bstride);
        const int Cp = (C + KC - 1)/KC*KC;
        const size_t smem = (size_t)(Cp*TM + KC*TN + TM*(TN+1) + TN) * 4;
        k_knn<<<dim3(N_/TM, B_), 256, smem>>>(knn_base, C, bstride);

        const int c4n = Cpad >> 2;
        const int totw = 2*c4n*O;
        k_prep_w<<<(totw + 255)/256, 256>>>(W[s], C, Cpad, O, 2);
        k_clear<<<2, 256>>>();

        const float* gsrc = (s == 0) ? x0nc : xnc;
        const int CS   = (s == 0) ? 4 : CB;
        const int coff = (s == 0) ? 0 : st[s].cin;
        k_conv_edge<<<B_*N_/PP, O>>>(gsrc, CS, coff, Cpad, O, wt, wt + c4n*O);

        const float invcnt = 1.f / (float)(B_*N_*K_);
        k_fin_edge<<<(B_*N_*O + 255)/256, 256>>>(O, st[s].cout, G[s], Bt[s], invcnt);
    }

    // block 5
    k_prep_w<<<(1*(CB/4)*512 + 255)/256, 256>>>(W[4], 512, 512, 512, 1);
    k_clear<<<2, 256>>>();
    k_conv5<<<B_*N_/PP, 512>>>(wt);
    k_fin5<<<dim3(N_/32, CB/32, B_), dim3(32, 8)>>>(G[4], Bt[4], out);
}

// round 2
// speedup vs baseline: 1.1488x; 1.1488x over previous
#include <cuda_runtime.h>
#include <math.h>

#define B_ 8
#define N_ 2048
#define K_ 4
#define CB 512
#define PP 8
#define S_ 2
#define TMK 128
#define TNK 128

// f32x2 packed math (Blackwell dual-rate fp32 path)
#define FFMA2(d,a,b) asm("fma.rn.f32x2 %0, %1, %2, %0;" : "+l"(d) : "l"(a), "l"(b))
__device__ __forceinline__ unsigned long long pack2(float lo, float hi) {
    unsigned long long r;
    asm("mov.b64 %0, {%1,%2};" : "=l"(r) : "f"(lo), "f"(hi));
    return r;
}
__device__ __forceinline__ float2 unpack2(unsigned long long v) {
    float2 f;
    asm("mov.b64 {%0,%1}, %2;" : "=f"(f.x), "=f"(f.y) : "l"(v));
    return f;
}

// ---------------- scratch ----------------
__device__ float g_xcn[(size_t)B_*CB*N_];
__device__ float g_xnc[(size_t)B_*N_*CB];
__device__ float4 g_x0nc[(size_t)B_*N_];
__device__ float g_xx[(size_t)B_*N_];
__device__ float4 g_cv4[(size_t)B_*N_*S_];
__device__ int4   g_ci4[(size_t)B_*N_*S_];
__device__ float g_mx[(size_t)B_*N_*256];
__device__ float g_mn[(size_t)B_*N_*256];
__device__ float g_y5[(size_t)B_*N_*512];
__device__ float g_sum[5*512];
__device__ float g_ssq[5*512];
__device__ float4 g_wT4[90112];

// ---------------- prep: pack all weights + clear stats ----------------
__global__ void k_prep_w_all(const float* __restrict__ w1, const float* __restrict__ w2,
                             const float* __restrict__ w3, const float* __restrict__ w4,
                             const float* __restrict__ w5) {
    int t = blockIdx.x*blockDim.x + threadIdx.x;
    if (t < 5*512) { g_sum[t] = 0.f; g_ssq[t] = 0.f; }
    if (t >= 88192) return;
    const float* w; int realC, O, parts, lt;
    if      (t < 128)   { w = w1; realC = 3;   O = 64;  parts = 2; lt = t; }
    else if (t < 2176)  { w = w2; realC = 64;  O = 64;  parts = 2; lt = t - 128; }
    else if (t < 6272)  { w = w3; realC = 64;  O = 128; parts = 2; lt = t - 2176; }
    else if (t < 22656) { w = w4; realC = 128; O = 256; parts = 2; lt = t - 6272; }
    else                { w = w5; realC = 512; O = 512; parts = 1; lt = t - 22656; }
    int padC = (realC == 3) ? 4 : realC;
    int c4n = padC >> 2;
    int o = lt % O; int r = lt / O; int c4 = r % c4n; int part = r / c4n;
    float4 v; float* pv = (float*)&v;
    #pragma unroll
    for (int j = 0; j < 4; j++) {
        int c = c4*4 + j;
        pv[j] = (c < realC) ? w[o*(parts*realC) + part*realC + c] : 0.f;
    }
    g_wT4[t] = v;
}

__global__ void k_prep_x0(const float* __restrict__ x) {
    int t = blockIdx.x*blockDim.x + threadIdx.x;
    if (t >= B_*N_) return;
    int b = t >> 11, n = t & (N_-1);
    float vx = x[(b*3+0)*N_ + n];
    float vy = x[(b*3+1)*N_ + n];
    float vz = x[(b*3+2)*N_ + n];
    g_x0nc[t] = make_float4(vx, vy, vz, 0.f);
    g_xx[t] = vx*vx + vy*vy + vz*vz;
}

// ---------------- knn: 128x128 tiled distance GEMM (FFMA2) + top-4 ----------------
template<int C>
__global__ void __launch_bounds__(256) k_knn2(const float* __restrict__ base, long bstride) {
    constexpr int KCc = (C <= 4) ? 4 : 16;
    extern __shared__ float sm[];
    float* Ash = sm;                         // [KCc][TMK]
    float* Bsh = Ash + KCc*TMK;              // [KCc][TNK]
    float* PD  = Bsh + KCc*TNK;              // [TMK][TNK+1]
    float* xxc = PD + TMK*(TNK+1);           // [TNK]

    const int b  = blockIdx.z;
    const int s  = blockIdx.y;
    const int n0 = blockIdx.x * TMK;
    const float* X = base + (long)b * bstride;
    const float* xxg = g_xx + b*N_;
    const int tid = threadIdx.x;
    const int ty = tid >> 4, tx = tid & 15;
    const int r0 = ty*8, c0 = tx*8;

    float xxr[8];
    #pragma unroll
    for (int i = 0; i < 8; i++) xxr[i] = xxg[n0 + r0 + i];

    float v0=-3.4e38f, v1=-3.4e38f, v2=-3.4e38f, v3=-3.4e38f;
    int   i0=0, i1=0, i2=0, i3=0;

    for (int mb = 0; mb < (N_/S_)/TNK; mb++) {
        const int m0 = s*(N_/S_) + mb*TNK;
        if (tid < TNK) xxc[tid] = xxg[m0 + tid];
        unsigned long long acc[4][8];
        #pragma unroll
        for (int i = 0; i < 4; i++)
            #pragma unroll
            for (int j = 0; j < 8; j++) acc[i][j] = 0ull;

        for (int kc = 0; kc < C; kc += KCc) {
            #pragma unroll
            for (int t = tid; t < KCc*TMK; t += 256) {
                int c = t >> 7, r = t & (TMK-1);
                int cg = kc + c;
                Ash[t] = (cg < C) ? X[(long)cg*N_ + n0 + r] : 0.f;
            }
            #pragma unroll
            for (int t = tid; t < KCc*TNK; t += 256) {
                int c = t >> 7, m = t & (TNK-1);
                int cg = kc + c;
                Bsh[t] = (cg < C) ? X[(long)cg*N_ + m0 + m] : 0.f;
            }
            __syncthreads();
            #pragma unroll 4
            for (int cc = 0; cc < KCc; cc++) {
                const ulonglong2* ap = (const ulonglong2*)&Ash[cc*TMK + r0];
                ulonglong2 aA = ap[0], aB = ap[1];
                unsigned long long ar[4] = {aA.x, aA.y, aB.x, aB.y};
                const float4* bp = (const float4*)&Bsh[cc*TNK + c0];
                float4 bA = bp[0], bB = bp[1];
                unsigned long long bd[8];
                bd[0] = pack2(bA.x, bA.x); bd[1] = pack2(bA.y, bA.y);
                bd[2] = pack2(bA.z, bA.z); bd[3] = pack2(bA.w, bA.w);
                bd[4] = pack2(bB.x, bB.x); bd[5] = pack2(bB.y, bB.y);
                bd[6] = pack2(bB.z, bB.z); bd[7] = pack2(bB.w, bB.w);
                #pragma unroll
                for (int i = 0; i < 4; i++)
                    #pragma unroll
                    for (int j = 0; j < 8; j++)
                        FFMA2(acc[i][j], ar[i], bd[j]);
            }
            __syncthreads();
        }
        // pd = 2*inner - xx_row - xx_col
        #pragma unroll
        for (int i = 0; i < 4; i++)
            #pragma unroll
            for (int j = 0; j < 8; j++) {
                float2 v = unpack2(acc[i][j]);
                float xc = xxc[c0 + j];
                PD[(r0+2*i)*(TNK+1) + c0 + j]   = 2.f*v.x - xxr[2*i]   - xc;
                PD[(r0+2*i+1)*(TNK+1) + c0 + j] = 2.f*v.y - xxr[2*i+1] - xc;
            }
        __syncthreads();
        if (tid < TMK) {
            const float* row = &PD[tid*(TNK+1)];
            for (int j = 0; j < TNK; j++) {
                float p = row[j];
                if (p > v3) {
                    int m = m0 + j;
                    if (p > v1) {
                        if (p > v0) { v3=v2;i3=i2; v2=v1;i2=i1; v1=v0;i1=i0; v0=p;i0=m; }
                        else        { v3=v2;i3=i2; v2=v1;i2=i1; v1=p;i1=m; }
                    } else {
                        if (p > v2) { v3=v2;i3=i2; v2=p;i2=m; }
                        else        { v3=p;i3=m; }
                    }
                }
            }
        }
        __syncthreads();
    }
    if (tid < TMK) {
        int ci = (b*N_ + n0 + tid)*S_ + s;
        g_cv4[ci] = make_float4(v0, v1, v2, v3);
        g_ci4[ci] = make_int4(i0, i1, i2, i3);
    }
}

// ---------------- edge conv: merge candidates + gather + FFMA2 conv + minmax ----------------
__global__ void k_conv_edge(const float* __restrict__ xnc, int CS, int coff,
                            int Cpad, int O, int stage,
                            const float4* __restrict__ wn4,
                            const float4* __restrict__ wc4) {
    __shared__ float4 sf4[PP*5*128/4];
    __shared__ int sidx[PP*K_];
    const int bid = blockIdx.x;
    const int b  = bid >> 8;             // N_/PP = 256 blocks per batch
    const int n0 = (bid & 255) * PP;
    const int o  = threadIdx.x;

    if (o < PP) {
        float bv0=-3.4e38f, bv1=-3.4e38f, bv2=-3.4e38f, bv3=-3.4e38f;
        int bi0=0, bi1=0, bi2=0, bi3=0;
        int cbase = (b*N_ + n0 + o)*S_;
        #pragma unroll
        for (int s2 = 0; s2 < S_; s2++) {
            float4 cv = g_cv4[cbase + s2];
            int4   ci = g_ci4[cbase + s2];
            float vv[4] = {cv.x, cv.y, cv.z, cv.w};
            int   ii[4] = {ci.x, ci.y, ci.z, ci.w};
            #pragma unroll
            for (int q = 0; q < 4; q++) {
                float p = vv[q]; int m = ii[q];
                if (p > bv3) {
                    if (p > bv1) {
                        if (p > bv0) { bv3=bv2;bi3=bi2; bv2=bv1;bi2=bi1; bv1=bv0;bi1=bi0; bv0=p;bi0=m; }
                        else         { bv3=bv2;bi3=bi2; bv2=bv1;bi2=bi1; bv1=p;bi1=m; }
                    } else {
                        if (p > bv2) { bv3=bv2;bi3=bi2; bv2=p;bi2=m; }
                        else         { bv3=p;bi3=m; }
                    }
                }
            }
        }
        sidx[o*4+0]=bi0; sidx[o*4+1]=bi1; sidx[o*4+2]=bi2; sidx[o*4+3]=bi3;
    }
    __syncthreads();

    const int c4n = Cpad >> 2;
    const int tot4 = PP*5*c4n;
    for (int t = o; t < tot4; t += O) {
        int c4 = t % c4n; int r = t / c4n; int v = r % 5; int p = r / 5;
        int m = (v == 0) ? (n0 + p) : sidx[p*4 + v - 1];
        sf4[(p*5 + v)*c4n + c4] = ((const float4*)&xnc[((long)b*N_ + m)*CS + coff])[c4];
    }
    __syncthreads();

    const float* sf = (const float*)sf4;
    unsigned long long yc2[PP], yn2[PP][K_];
    #pragma unroll
    for (int p = 0; p < PP; p++) {
        yc2[p] = 0ull;
        #pragma unroll
        for (int k = 0; k < K_; k++) yn2[p][k] = 0ull;
    }
    const ulonglong2* wnp = (const ulonglong2*)wn4;
    const ulonglong2* wcp = (const ulonglong2*)wc4;
    for (int c4 = 0; c4 < c4n; c4++) {
        ulonglong2 wn = wnp[c4*O + o];
        ulonglong2 wc = wcp[c4*O + o];
        #pragma unroll
        for (int p = 0; p < PP; p++) {
            ulonglong2 f = *(const ulonglong2*)&sf[(p*5)*Cpad + c4*4];
            FFMA2(yc2[p], wc.x, f.x);
            FFMA2(yc2[p], wc.y, f.y);
            #pragma unroll
            for (int k = 0; k < K_; k++) {
                ulonglong2 g = *(const ulonglong2*)&sf[(p*5 + k + 1)*Cpad + c4*4];
                FFMA2(yn2[p][k], wn.x, g.x);
                FFMA2(yn2[p][k], wn.y, g.y);
            }
        }
    }
    float s1 = 0.f, s2 = 0.f;
    #pragma unroll
    for (int p = 0; p < PP; p++) {
        float2 cu = unpack2(yc2[p]);
        float ycv = cu.x + cu.y;
        float mmax = -3.4e38f, mmin = 3.4e38f;
        #pragma unroll
        for (int k = 0; k < K_; k++) {
            float2 nu = unpack2(yn2[p][k]);
            float y = nu.x + nu.y + ycv;
            mmax = fmaxf(mmax, y); mmin = fminf(mmin, y);
            s1 += y; s2 += y*y;
        }
        long oi = ((long)(b*N_ + n0 + p))*O + o;
        g_mx[oi] = mmax; g_mn[oi] = mmin;
    }
    atomicAdd(&g_sum[stage*512 + o], s1);
    atomicAdd(&g_ssq[stage*512 + o], s2);
}

// ---------------- BN finalize + relu + write both layouts + norms for next knn ----------------
__global__ void k_fin_edge(int O, int coff, int stage, const float* __restrict__ gm,
                           const float* __restrict__ bt, float invcnt) {
    __shared__ float red[256];
    const int bn = blockIdx.x;
    const int o  = threadIdx.x;
    const int so = stage*512 + o;
    float mean = g_sum[so] * invcnt;
    float var  = g_ssq[so] * invcnt - mean*mean;
    float a  = gm[o] * rsqrtf(var + 1e-5f);
    float c0 = bt[o] - mean*a;
    long t = (long)bn*O + o;
    float z = (a >= 0.f) ? (a*g_mx[t] + c0) : (a*g_mn[t] + c0);
    z = fmaxf(z, 0.f);
    int b = bn >> 11, n = bn & (N_-1);
    g_xnc[(long)bn*CB + coff + o] = z;
    g_xcn[((long)b*CB + coff + o)*N_ + n] = z;
    red[o] = z*z;
    __syncthreads();
    for (int st = O >> 1; st > 0; st >>= 1) {
        if (o < st) red[o] += red[o + st];
        __syncthreads();
    }
    if (o == 0) g_xx[bn] = red[0];
}

// ---------------- block 5: 512x512 conv (FFMA2) + stats ----------------
__global__ void __launch_bounds__(512) k_conv5(const float4* __restrict__ wT) {
    __shared__ float4 sf4[PP*CB/4];
    const int bid = blockIdx.x;
    const int b  = bid >> 8;
    const int n0 = (bid & 255) * PP;
    const int o  = threadIdx.x;
    const float4* src = (const float4*)&g_xnc[((long)b*N_ + n0)*CB];
    for (int t = o; t < PP*CB/4; t += 512) sf4[t] = src[t];
    __syncthreads();
    unsigned long long y2[PP];
    #pragma unroll
    for (int p = 0; p < PP; p++) y2[p] = 0ull;
    const ulonglong2* wp = (const ulonglong2*)wT;
    const ulonglong2* fp = (const ulonglong2*)sf4;
    for (int c4 = 0; c4 < CB/4; c4++) {
        ulonglong2 w = wp[c4*512 + o];
        #pragma unroll
        for (int p = 0; p < PP; p++) {
            ulonglong2 f = fp[p*(CB/4) + c4];
            FFMA2(y2[p], w.x, f.x);
            FFMA2(y2[p], w.y, f.y);
        }
    }
    float s1 = 0.f, s2 = 0.f;
    #pragma unroll
    for (int p = 0; p < PP; p++) {
        float2 u = unpack2(y2[p]);
        float y = u.x + u.y;
        s1 += y; s2 += y*y;
        g_y5[((long)b*N_ + n0 + p)*CB + o] = y;
    }
    atomicAdd(&g_sum[4*512 + o], s1);
    atomicAdd(&g_ssq[4*512 + o], s2);
}

__global__ void k_fin5(const float* __restrict__ gm, const float* __restrict__ bt,
                       float* __restrict__ out) {
    __shared__ float tile[32][33];
    const int b  = blockIdx.z;
    const int o0 = blockIdx.y*32;
    const int n0 = blockIdx.x*32;
    const int tx = threadIdx.x, ty0 = threadIdx.y;
    const float invcnt = 1.f / (float)(B_*N_);
    int o = o0 + tx;
    float mean = g_sum[4*512 + o] * invcnt;
    float var  = g_ssq[4*512 + o] * invcnt - mean*mean;
    float a  = gm[o] * rsqrtf(var + 1e-5f);
    float c0 = bt[o] - mean*a;
    #pragma unroll
    for (int i = 0; i < 4; i++) {
        int ty = ty0 + i*8;
        float y = g_y5[((long)b*N_ + n0 + ty)*CB + o];
        tile[ty][tx] = tanhf(a*y + c0);
    }
    __syncthreads();
    #pragma unroll
    for (int i = 0; i < 4; i++) {
        int ty = ty0 + i*8;
        out[((long)b*CB + o0 + ty)*N_ + n0 + tx] = tile[tx][ty];
    }
}

// ---------------- launch ----------------
extern "C" void kernel_launch(void* const* d_in, const int* in_sizes, int n_in,
                              void* d_out, int out_size) {
    const float* x = (const float*)d_in[0];
    const float* W[5]; const float* G[5]; const float* Bt[5];
    for (int i = 0; i < 5; i++) {
        W[i]  = (const float*)d_in[1 + 3*i];
        G[i]  = (const float*)d_in[2 + 3*i];
        Bt[i] = (const float*)d_in[3 + 3*i];
    }
    float* out = (float*)d_out;

    float* xcn;   cudaGetSymbolAddress((void**)&xcn,  g_xcn);
    float* xnc;   cudaGetSymbolAddress((void**)&xnc,  g_xnc);
    float* x0nc;  cudaGetSymbolAddress((void**)&x0nc, g_x0nc);
    float4* wt;   cudaGetSymbolAddress((void**)&wt,   g_wT4);

    const int SM3  = (4*TMK + 4*TNK + TMK*(TNK+1) + TNK) * 4;
    const int SM16 = (16*TMK + 16*TNK + TMK*(TNK+1) + TNK) * 4;
    cudaFuncSetAttribute(k_knn2<3>,   cudaFuncAttributeMaxDynamicSharedMemorySize, SM3);
    cudaFuncSetAttribute(k_knn2<64>,  cudaFuncAttributeMaxDynamicSharedMemorySize, SM16);
    cudaFuncSetAttribute(k_knn2<128>, cudaFuncAttributeMaxDynamicSharedMemorySize, SM16);

    k_prep_w_all<<<(88192 + 255)/256, 256>>>(W[0], W[1], W[2], W[3], W[4]);
    k_prep_x0<<<(B_*N_ + 255)/256, 256>>>(x);

    const dim3 kg(N_/TMK, S_, B_);
    const float invE = 1.f / (float)(B_*N_*K_);
    // weight region starts (float4 units) and c4n*O splits
    const int wstart[5] = {0, 128, 2176, 6272, 22656};

    // stage 0: C=3
    k_knn2<3><<<kg, 256, SM3>>>(x, (long)3*N_);
    k_conv_edge<<<B_*N_/PP, 64>>>(x0nc, 4, 0, 4, 64, 0, wt + wstart[0], wt + wstart[0] + 1*64);
    k_fin_edge<<<B_*N_, 64>>>(64, 0, 0, G[0], Bt[0], invE);
    // stage 1: C=64 (x1 at ch 0)
    k_knn2<64><<<kg, 256, SM16>>>(xcn + (long)0*N_, (long)CB*N_);
    k_conv_edge<<<B_*N_/PP, 64>>>(xnc, CB, 0, 64, 64, 1, wt + wstart[1], wt + wstart[1] + 16*64);
    k_fin_edge<<<B_*N_, 64>>>(64, 64, 1, G[1], Bt[1], invE);
    // stage 2: C=64 (x2 at ch 64)
    k_knn2<64><<<kg, 256, SM16>>>(xcn + (long)64*N_, (long)CB*N_);
    k_conv_edge<<<B_*N_/PP, 128>>>(xnc, CB, 64, 64, 128, 2, wt + wstart[2], wt + wstart[2] + 16*128);
    k_fin_edge<<<B_*N_, 128>>>(128, 128, 2, G[2], Bt[2], invE);
    // stage 3: C=128 (x3 at ch 128)
    k_knn2<128><<<kg, 256, SM16>>>(xcn + (long)128*N_, (long)CB*N_);
    k_conv_edge<<<B_*N_/PP, 256>>>(xnc, CB, 128, 128, 256, 3, wt + wstart[3], wt + wstart[3] + 32*256);
    k_fin_edge<<<B_*N_, 256>>>(256, 256, 3, G[3], Bt[3], invE);
    // block 5
    k_conv5<<<B_*N_/PP, 512>>>(wt + wstart[4]);
    k_fin5<<<dim3(N_/32, CB/32, B_), dim3(32, 8)>>>(G[4], Bt[4], out);
}